// round 7
// baseline (speedup 1.0000x reference)
#include <cuda_runtime.h>
#include <cuda_bf16.h>
#include <cstdint>

#define SEQ   2048
#define NX    768
#define NH    12
#define HD    64
#define BSZ   2
#define MROWS (BSZ*SEQ)

// ---------------- flash attention config (unchanged, known-passing) --------
#define BQ 128
#define BK 64
#define FLASH_SMEM ((BQ*HD + BK*(HD+1) + BK*(HD+1) + BQ*(BK+1))*4)

// ---------------- mma.sync GEMM config -------------------------------------
#define TM 128
#define TN 128
#define TK 32                  // fp32 K elements staged per iteration
#define NSTAGE (NX / TK)       // 24

#define ASTR 20                // words per A row (16 data + 4 pad) -> conflict-free frags
#define BSTR 136               // words per B k2-row (128 data + 8 pad) -> conflict-free frags
#define SM_A_HI 0
#define SM_A_LO (128 * ASTR)                 // 2560
#define SM_B_HI (2 * 128 * ASTR)             // 5120
#define SM_B_LO (2 * 128 * ASTR + 16 * BSTR) // 7296
#define GEMM_SMEM_WORDS (2 * 128 * ASTR + 2 * 16 * BSTR)  // 9472 words = 37888 B

// Scratch (allocation-free rule: __device__ globals).
__device__ float g_q[(size_t)BSZ*SEQ*NX];
__device__ float g_k[(size_t)BSZ*SEQ*NX];
__device__ float g_v[(size_t)BSZ*SEQ*NX];
__device__ float g_att[(size_t)BSZ*SEQ*NX];

// mma.sync m16n8k16 bf16 -> f32, D += A*B
#define MMA_BF16(d, a, b0, b1)                                              \
    asm volatile(                                                           \
        "mma.sync.aligned.m16n8k16.row.col.f32.bf16.bf16.f32 "              \
        "{%0,%1,%2,%3}, {%4,%5,%6,%7}, {%8,%9}, {%0,%1,%2,%3};"             \
        : "+f"((d)[0]), "+f"((d)[1]), "+f"((d)[2]), "+f"((d)[3])            \
        : "r"((a)[0]), "r"((a)[1]), "r"((a)[2]), "r"((a)[3]),               \
          "r"(b0), "r"(b1))

// hi/lo bf16 split of two fp32, packed into two .b32 (lo16 = first element)
__device__ __forceinline__ void pack2(float x, float y,
                                      uint32_t& hi, uint32_t& lo) {
    __nv_bfloat16 hx = __float2bfloat16_rn(x);
    __nv_bfloat16 hy = __float2bfloat16_rn(y);
    __nv_bfloat16 lx = __float2bfloat16_rn(x - __bfloat162float(hx));
    __nv_bfloat16 ly = __float2bfloat16_rn(y - __bfloat162float(hy));
    hi = (uint32_t)__bfloat16_as_ushort(hx) | ((uint32_t)__bfloat16_as_ushort(hy) << 16);
    lo = (uint32_t)__bfloat16_as_ushort(lx) | ((uint32_t)__bfloat16_as_ushort(ly) << 16);
}

// ---------------------------------------------------------------------------
// Tensor-core GEMM: C[4096, Ncols] = A[4096,768] @ B[768,Ncols] + bias
// bf16x3 emulation (Ahi*Bhi + Alo*Bhi + Ahi*Blo), fp32 accumulators.
// mode 1: dest split into g_q/g_k/g_v (Ncols=2304, each row stride NX)
// mode 2: A := g_att, dest = C (Ncols=768)
// 8 warps: warp_m = wid>>2 (2), warp_n = wid&3 (4); warp tile 64x32.
// ---------------------------------------------------------------------------
__global__ __launch_bounds__(256, 2)
void gemm_mma(const float* __restrict__ A, const float* __restrict__ B,
              const float* __restrict__ bias, float* __restrict__ C,
              int Ncols, int mode)
{
    __shared__ uint32_t smw[GEMM_SMEM_WORDS];

    const int tid  = threadIdx.x;
    const int lane = tid & 31, wid = tid >> 5;
    const int warp_m = wid >> 2;       // 0..1
    const int warp_n = wid & 3;        // 0..3
    const int m0 = blockIdx.y * TM;
    const int n0 = blockIdx.x * TN;
    const float* Ap = (mode == 2) ? g_att : A;

    const int g  = lane >> 2;          // 0..7  (fragment row / col group)
    const int tg = lane & 3;           // 0..3  (k-pair group)

    float acc[4][4][4];                // [m-tile][n-tile][c0..c3]
#pragma unroll
    for (int mt = 0; mt < 4; mt++)
#pragma unroll
        for (int nt = 0; nt < 4; nt++)
#pragma unroll
            for (int j = 0; j < 4; j++) acc[mt][nt][j] = 0.f;

    for (int s = 0; s < NSTAGE; s++) {
        const int k0 = s * TK;

        // ---- stage A tile [128][32] fp32 -> hi/lo bf16 pairs -------------
#pragma unroll
        for (int it = 0; it < 4; it++) {
            const int idx = tid + it * 256;       // 1024 float4 slots
            const int row = idx >> 3, c4 = idx & 7;
            float4 v = *(const float4*)(Ap + (size_t)(m0 + row) * NX + k0 + c4 * 4);
            uint32_t h0, l0, h1, l1;
            pack2(v.x, v.y, h0, l0);
            pack2(v.z, v.w, h1, l1);
            const int w = row * ASTR + c4 * 2;
            smw[SM_A_HI + w]     = h0;
            smw[SM_A_HI + w + 1] = h1;
            smw[SM_A_LO + w]     = l0;
            smw[SM_A_LO + w + 1] = l1;
        }
        // ---- stage B tile: B[k0..k0+31][n0..n0+127] -> smem [k2][n] ------
#pragma unroll
        for (int it = 0; it < 8; it++) {
            const int idx = tid + it * 256;       // 2048 word slots
            const int n = idx & 127, k2 = idx >> 7;
            const float* bp = B + (size_t)(k0 + 2 * k2) * Ncols + n0 + n;
            uint32_t hi, lo;
            pack2(bp[0], bp[Ncols], hi, lo);
            smw[SM_B_HI + k2 * BSTR + n] = hi;
            smw[SM_B_LO + k2 * BSTR + n] = lo;
        }
        __syncthreads();

        // ---- two k16 chunks of MMAs --------------------------------------
#pragma unroll
        for (int c = 0; c < 2; c++) {
            uint32_t ah[4][4], al[4][4];
#pragma unroll
            for (int mt = 0; mt < 4; mt++) {
                const int r = warp_m * 64 + mt * 16 + g;
                const int base = r * ASTR + c * 8 + tg;
                ah[mt][0] = smw[SM_A_HI + base];
                ah[mt][1] = smw[SM_A_HI + base + 8 * ASTR];
                ah[mt][2] = smw[SM_A_HI + base + 4];
                ah[mt][3] = smw[SM_A_HI + base + 8 * ASTR + 4];
                al[mt][0] = smw[SM_A_LO + base];
                al[mt][1] = smw[SM_A_LO + base + 8 * ASTR];
                al[mt][2] = smw[SM_A_LO + base + 4];
                al[mt][3] = smw[SM_A_LO + base + 8 * ASTR + 4];
            }
#pragma unroll
            for (int nt = 0; nt < 4; nt++) {
                const int ncol = warp_n * 32 + nt * 8 + g;
                const int kb = c * 8 + tg;
                const uint32_t bh0 = smw[SM_B_HI + kb * BSTR + ncol];
                const uint32_t bh1 = smw[SM_B_HI + (kb + 4) * BSTR + ncol];
                const uint32_t bl0 = smw[SM_B_LO + kb * BSTR + ncol];
                const uint32_t bl1 = smw[SM_B_LO + (kb + 4) * BSTR + ncol];
#pragma unroll
                for (int mt = 0; mt < 4; mt++) {
                    MMA_BF16(acc[mt][nt], ah[mt], bh0, bh1);
                    MMA_BF16(acc[mt][nt], al[mt], bh0, bh1);
                    MMA_BF16(acc[mt][nt], ah[mt], bl0, bl1);
                }
            }
        }
        __syncthreads();
    }

    // ---- epilogue: fragment -> gmem (+bias) -------------------------------
    float* dst; int ncolbase; size_t stride;
    if (mode == 1) {
        const int which = n0 / NX;       // whole 128-col tile in one segment
        dst = (which == 0) ? g_q : (which == 1) ? g_k : g_v;
        ncolbase = n0 - which * NX; stride = NX;
    } else {
        dst = C; ncolbase = n0; stride = (size_t)Ncols;
    }
#pragma unroll
    for (int mt = 0; mt < 4; mt++) {
        const int r0 = m0 + warp_m * 64 + mt * 16 + g;
#pragma unroll
        for (int nt = 0; nt < 4; nt++) {
            const int gc = n0 + warp_n * 32 + nt * 8 + tg * 2;   // global col
            const int lc = ncolbase + warp_n * 32 + nt * 8 + tg * 2;
            const float b0 = bias[gc], b1 = bias[gc + 1];
            float2 o0, o1;
            o0.x = acc[mt][nt][0] + b0; o0.y = acc[mt][nt][1] + b1;
            o1.x = acc[mt][nt][2] + b0; o1.y = acc[mt][nt][3] + b1;
            *(float2*)(dst + (size_t)r0 * stride + lc)       = o0;
            *(float2*)(dst + (size_t)(r0 + 8) * stride + lc) = o1;
        }
    }
}

// ---------------------------------------------------------------------------
// Flash attention, fp32 (unchanged from passing round-3 kernel).
// ---------------------------------------------------------------------------
__global__ __launch_bounds__(256, 2)
void flash_kernel(const float* __restrict__ am_g)
{
    extern __shared__ float smf[];
    float* Qs = smf;
    float* Ks = Qs + BQ * HD;
    float* Vs = Ks + BK * (HD + 1);
    float* Ps = Vs + BK * (HD + 1);

    const int tid = threadIdx.x;
    const int qt = blockIdx.x, h = blockIdx.y, b = blockIdx.z;
    const size_t headoff = (size_t)b * SEQ * NX + (size_t)h * SEQ * HD;
    const float* Qh = g_q + headoff;
    const float* Kh = g_k + headoff;
    const float* Vh = g_v + headoff;
    const float* am = am_g + (size_t)b * SEQ;
    const int q0 = qt * BQ;

    for (int idx = tid; idx < BQ * (HD / 4); idx += 256) {
        const int row = idx >> 4;
        const int c4  = (idx & 15) * 4;
        *(float4*)(Qs + row * HD + c4) =
            *(const float4*)(Qh + (size_t)(q0 + row) * HD + c4);
    }

    const int ty = tid >> 4, tx = tid & 15;
    const int qr0 = ty * 8, kc0 = tx * 4;

    float m_i[8], l_i[8], O[8][4];
#pragma unroll
    for (int i = 0; i < 8; i++) {
        m_i[i] = -1e30f; l_i[i] = 0.f;
#pragma unroll
        for (int j = 0; j < 4; j++) O[i][j] = 0.f;
    }

    const int ktmax = 2 * qt + 1;
    for (int kt = 0; kt <= ktmax; kt++) {
        __syncthreads();
        const int k0 = kt * BK;
        for (int idx = tid; idx < BK * (HD / 4); idx += 256) {
            const int row = idx >> 4;
            const int c4  = (idx & 15) * 4;
            float4 kv = *(const float4*)(Kh + (size_t)(k0 + row) * HD + c4);
            float4 vv = *(const float4*)(Vh + (size_t)(k0 + row) * HD + c4);
            float* kd = Ks + row * (HD + 1) + c4;
            kd[0] = kv.x; kd[1] = kv.y; kd[2] = kv.z; kd[3] = kv.w;
            float* vd = Vs + row * (HD + 1) + c4;
            vd[0] = vv.x; vd[1] = vv.y; vd[2] = vv.z; vd[3] = vv.w;
        }
        __syncthreads();

        float s[8][4];
#pragma unroll
        for (int i = 0; i < 8; i++)
#pragma unroll
            for (int j = 0; j < 4; j++) s[i][j] = 0.f;

#pragma unroll 4
        for (int d = 0; d < HD; d++) {
            float kr[4];
#pragma unroll
            for (int j = 0; j < 4; j++) kr[j] = Ks[(kc0 + j) * (HD + 1) + d];
#pragma unroll
            for (int i = 0; i < 8; i++) {
                const float qv = Qs[(qr0 + i) * HD + d];
#pragma unroll
                for (int j = 0; j < 4; j++) s[i][j] = fmaf(qv, kr[j], s[i][j]);
            }
        }

        float amr[4];
#pragma unroll
        for (int j = 0; j < 4; j++) amr[j] = am[k0 + kc0 + j];

#pragma unroll
        for (int i = 0; i < 8; i++) {
            const int qg = q0 + qr0 + i;
#pragma unroll
            for (int j = 0; j < 4; j++) {
                const int kg = k0 + kc0 + j;
                s[i][j] = (kg <= qg) ? fmaf(s[i][j], 0.125f, amr[j])
                                     : (-10000.0f + amr[j]);
            }
        }

#pragma unroll
        for (int i = 0; i < 8; i++) {
            float tm = fmaxf(fmaxf(s[i][0], s[i][1]), fmaxf(s[i][2], s[i][3]));
#pragma unroll
            for (int off = 8; off >= 1; off >>= 1)
                tm = fmaxf(tm, __shfl_xor_sync(0xffffffffu, tm, off));
            const float mn = fmaxf(m_i[i], tm);
            const float corr = __expf(m_i[i] - mn);
            m_i[i] = mn;
            float rs = 0.f;
#pragma unroll
            for (int j = 0; j < 4; j++) {
                const float p = __expf(s[i][j] - mn);
                s[i][j] = p;
                rs += p;
            }
#pragma unroll
            for (int off = 8; off >= 1; off >>= 1)
                rs += __shfl_xor_sync(0xffffffffu, rs, off);
            l_i[i] = l_i[i] * corr + rs;
#pragma unroll
            for (int j = 0; j < 4; j++) O[i][j] *= corr;
            float* pd = Ps + (qr0 + i) * (BK + 1) + kc0;
#pragma unroll
            for (int j = 0; j < 4; j++) pd[j] = s[i][j];
        }
        __syncthreads();

#pragma unroll 4
        for (int k = 0; k < BK; k++) {
            float vr[4];
#pragma unroll
            for (int j = 0; j < 4; j++) vr[j] = Vs[k * (HD + 1) + kc0 + j];
#pragma unroll
            for (int i = 0; i < 8; i++) {
                const float p = Ps[(qr0 + i) * (BK + 1) + k];
#pragma unroll
                for (int j = 0; j < 4; j++) O[i][j] = fmaf(p, vr[j], O[i][j]);
            }
        }
    }

#pragma unroll
    for (int i = 0; i < 8; i++) {
        const float inv = 1.0f / l_i[i];
        const int qg = q0 + qr0 + i;
        float4 o4;
        o4.x = O[i][0] * inv; o4.y = O[i][1] * inv;
        o4.z = O[i][2] * inv; o4.w = O[i][3] * inv;
        *(float4*)(g_att + ((size_t)b * SEQ + qg) * NX + h * HD + kc0) = o4;
    }
}

// ---------------------------------------------------------------------------
extern "C" void kernel_launch(void* const* d_in, const int* in_sizes, int n_in,
                              void* d_out, int out_size)
{
    const float* hidden = (const float*)d_in[0];
    const float* amask  = (const float*)d_in[1];
    const float* w_attn = (const float*)d_in[2];
    const float* b_attn = (const float*)d_in[3];
    const float* w_proj = (const float*)d_in[4];
    const float* b_proj = (const float*)d_in[5];
    float* out = (float*)d_out;

    cudaFuncSetAttribute(flash_kernel,
                         cudaFuncAttributeMaxDynamicSharedMemorySize, FLASH_SMEM);

    // 1) QKV projection (mma.sync bf16x3): split into g_q/g_k/g_v
    gemm_mma<<<dim3(3 * NX / TN, MROWS / TM), 256>>>(
        hidden, w_attn, b_attn, nullptr, 3 * NX, 1);

    // 2) Causal attention per (b, head), flash-style fp32
    flash_kernel<<<dim3(SEQ / BQ, NH, BSZ), 256, FLASH_SMEM>>>(amask);

    // 3) Output projection (mma.sync bf16x3): g_att @ w_proj + b -> d_out
    gemm_mma<<<dim3(NX / TN, MROWS / TM), 256>>>(
        nullptr, w_proj, b_proj, out, NX, 2);
}

// round 8
// speedup vs baseline: 2.5185x; 2.5185x over previous
#include <cuda_runtime.h>
#include <cuda_bf16.h>
#include <cstdint>

#define SEQ   2048
#define NX    768
#define NH    12
#define HD    64
#define BSZ   2
#define MROWS (BSZ*SEQ)
#define MBIAS -10000.0f

// ---------------- mma.sync GEMM config (unchanged, passing R7) -------------
#define TM 128
#define TN 128
#define TK 32
#define NSTAGE (NX / TK)

#define ASTR 20
#define BSTR 136
#define SM_A_HI 0
#define SM_A_LO (128 * ASTR)
#define SM_B_HI (2 * 128 * ASTR)
#define SM_B_LO (2 * 128 * ASTR + 16 * BSTR)
#define GEMM_SMEM_WORDS (2 * 128 * ASTR + 2 * 16 * BSTR)

// ---------------- flash mma config -----------------------------------------
#define BQ 128
#define BKT 64
#define KSTR 68                       // smem stride: bank = 4*tg+g, conflict-free
#define F_KHI 0
#define F_KLO (32 * KSTR)             // 2176
#define F_VHI (2 * 32 * KSTR)         // 4352
#define F_VLO (3 * 32 * KSTR)         // 6528
#define F_AMS (4 * 32 * KSTR)         // 8704
#define FLASH_SMEM_WORDS (4 * 32 * KSTR + 64)   // 8768 w = 35072 B

// Scratch (allocation-free rule: __device__ globals).
__device__ float g_q[(size_t)BSZ*SEQ*NX];
__device__ float g_k[(size_t)BSZ*SEQ*NX];
__device__ float g_v[(size_t)BSZ*SEQ*NX];
__device__ float g_att[(size_t)BSZ*SEQ*NX];

// mma.sync m16n8k16 bf16 -> f32, D += A*B
#define MMA_BF16(d, a, b0, b1)                                              \
    asm volatile(                                                           \
        "mma.sync.aligned.m16n8k16.row.col.f32.bf16.bf16.f32 "              \
        "{%0,%1,%2,%3}, {%4,%5,%6,%7}, {%8,%9}, {%0,%1,%2,%3};"             \
        : "+f"((d)[0]), "+f"((d)[1]), "+f"((d)[2]), "+f"((d)[3])            \
        : "r"((a)[0]), "r"((a)[1]), "r"((a)[2]), "r"((a)[3]),               \
          "r"(b0), "r"(b1))

// hi/lo bf16 split of two fp32 -> two packed b32 (low 16 bits = first elem)
__device__ __forceinline__ void pack2(float x, float y,
                                      uint32_t& hi, uint32_t& lo) {
    __nv_bfloat16 hx = __float2bfloat16_rn(x);
    __nv_bfloat16 hy = __float2bfloat16_rn(y);
    __nv_bfloat16 lx = __float2bfloat16_rn(x - __bfloat162float(hx));
    __nv_bfloat16 ly = __float2bfloat16_rn(y - __bfloat162float(hy));
    hi = (uint32_t)__bfloat16_as_ushort(hx) | ((uint32_t)__bfloat16_as_ushort(hy) << 16);
    lo = (uint32_t)__bfloat16_as_ushort(lx) | ((uint32_t)__bfloat16_as_ushort(ly) << 16);
}

// ---------------------------------------------------------------------------
// Tensor-core GEMM (identical to passing R7 kernel)
// ---------------------------------------------------------------------------
__global__ __launch_bounds__(256, 2)
void gemm_mma(const float* __restrict__ A, const float* __restrict__ B,
              const float* __restrict__ bias, float* __restrict__ C,
              int Ncols, int mode)
{
    __shared__ uint32_t smw[GEMM_SMEM_WORDS];

    const int tid  = threadIdx.x;
    const int lane = tid & 31, wid = tid >> 5;
    const int warp_m = wid >> 2;
    const int warp_n = wid & 3;
    const int m0 = blockIdx.y * TM;
    const int n0 = blockIdx.x * TN;
    const float* Ap = (mode == 2) ? g_att : A;

    const int g  = lane >> 2;
    const int tg = lane & 3;

    float acc[4][4][4];
#pragma unroll
    for (int mt = 0; mt < 4; mt++)
#pragma unroll
        for (int nt = 0; nt < 4; nt++)
#pragma unroll
            for (int j = 0; j < 4; j++) acc[mt][nt][j] = 0.f;

    for (int s = 0; s < NSTAGE; s++) {
        const int k0 = s * TK;
#pragma unroll
        for (int it = 0; it < 4; it++) {
            const int idx = tid + it * 256;
            const int row = idx >> 3, c4 = idx & 7;
            float4 v = *(const float4*)(Ap + (size_t)(m0 + row) * NX + k0 + c4 * 4);
            uint32_t h0, l0, h1, l1;
            pack2(v.x, v.y, h0, l0);
            pack2(v.z, v.w, h1, l1);
            const int w = row * ASTR + c4 * 2;
            smw[SM_A_HI + w]     = h0;
            smw[SM_A_HI + w + 1] = h1;
            smw[SM_A_LO + w]     = l0;
            smw[SM_A_LO + w + 1] = l1;
        }
#pragma unroll
        for (int it = 0; it < 8; it++) {
            const int idx = tid + it * 256;
            const int n = idx & 127, k2 = idx >> 7;
            const float* bp = B + (size_t)(k0 + 2 * k2) * Ncols + n0 + n;
            uint32_t hi, lo;
            pack2(bp[0], bp[Ncols], hi, lo);
            smw[SM_B_HI + k2 * BSTR + n] = hi;
            smw[SM_B_LO + k2 * BSTR + n] = lo;
        }
        __syncthreads();

#pragma unroll
        for (int c = 0; c < 2; c++) {
            uint32_t ah[4][4], al[4][4];
#pragma unroll
            for (int mt = 0; mt < 4; mt++) {
                const int r = warp_m * 64 + mt * 16 + g;
                const int base = r * ASTR + c * 8 + tg;
                ah[mt][0] = smw[SM_A_HI + base];
                ah[mt][1] = smw[SM_A_HI + base + 8 * ASTR];
                ah[mt][2] = smw[SM_A_HI + base + 4];
                ah[mt][3] = smw[SM_A_HI + base + 8 * ASTR + 4];
                al[mt][0] = smw[SM_A_LO + base];
                al[mt][1] = smw[SM_A_LO + base + 8 * ASTR];
                al[mt][2] = smw[SM_A_LO + base + 4];
                al[mt][3] = smw[SM_A_LO + base + 8 * ASTR + 4];
            }
#pragma unroll
            for (int nt = 0; nt < 4; nt++) {
                const int ncol = warp_n * 32 + nt * 8 + g;
                const int kb = c * 8 + tg;
                const uint32_t bh0 = smw[SM_B_HI + kb * BSTR + ncol];
                const uint32_t bh1 = smw[SM_B_HI + (kb + 4) * BSTR + ncol];
                const uint32_t bl0 = smw[SM_B_LO + kb * BSTR + ncol];
                const uint32_t bl1 = smw[SM_B_LO + (kb + 4) * BSTR + ncol];
#pragma unroll
                for (int mt = 0; mt < 4; mt++) {
                    MMA_BF16(acc[mt][nt], ah[mt], bh0, bh1);
                    MMA_BF16(acc[mt][nt], al[mt], bh0, bh1);
                    MMA_BF16(acc[mt][nt], ah[mt], bl0, bl1);
                }
            }
        }
        __syncthreads();
    }

    float* dst; int ncolbase; size_t stride;
    if (mode == 1) {
        const int which = n0 / NX;
        dst = (which == 0) ? g_q : (which == 1) ? g_k : g_v;
        ncolbase = n0 - which * NX; stride = NX;
    } else {
        dst = C; ncolbase = n0; stride = (size_t)Ncols;
    }
#pragma unroll
    for (int mt = 0; mt < 4; mt++) {
        const int r0 = m0 + warp_m * 64 + mt * 16 + g;
#pragma unroll
        for (int nt = 0; nt < 4; nt++) {
            const int gc = n0 + warp_n * 32 + nt * 8 + tg * 2;
            const int lc = ncolbase + warp_n * 32 + nt * 8 + tg * 2;
            const float b0 = bias[gc], b1 = bias[gc + 1];
            float2 o0, o1;
            o0.x = acc[mt][nt][0] + b0; o0.y = acc[mt][nt][1] + b1;
            o1.x = acc[mt][nt][2] + b0; o1.y = acc[mt][nt][3] + b1;
            *(float2*)(dst + (size_t)r0 * stride + lc)       = o0;
            *(float2*)(dst + (size_t)(r0 + 8) * stride + lc) = o1;
        }
    }
}

// ---------------------------------------------------------------------------
// Flash attention on mma.sync bf16x3. One CTA per (q-tile 128, head, batch).
// 8 warps, warp w owns q-rows [16w, 16w+16). Q pre-scaled by 0.125 (exact),
// held as register A-fragments (hi/lo). K/V staged per 64-tile in smem with
// stride-68 pair-packed layout (conflict-free fragment reads). P converted
// fp32->bf16 hi/lo in registers (S C-frag == PV A-frag layout).
// ---------------------------------------------------------------------------
__global__ __launch_bounds__(256, 2)
void flash_mma(const float* __restrict__ am_g)
{
    __shared__ uint32_t smw[FLASH_SMEM_WORDS];
    float* amsf = (float*)(smw + F_AMS);

    const int tid = threadIdx.x;
    const int lane = tid & 31, wid = tid >> 5;
    const int g = lane >> 2, tg = lane & 3;
    const int qt = blockIdx.x, h = blockIdx.y, b = blockIdx.z;
    const size_t headoff = (size_t)b * SEQ * NX + (size_t)h * SEQ * HD;
    const float* Qh = g_q + headoff;
    const float* Kh = g_k + headoff;
    const float* Vh = g_v + headoff;
    const float* am = am_g + (size_t)b * SEQ;
    const int q0 = qt * BQ;
    const int qg0 = q0 + wid * 16 + g;     // this thread's row 0 (row 1 = +8)
    const int qg1 = qg0 + 8;

    // ---- Q fragments (hi/lo), scaled by 1/8 exactly -----------------------
    uint32_t qfh[4][4], qfl[4][4];
#pragma unroll
    for (int kc = 0; kc < 4; kc++) {
        const float* p0 = Qh + (size_t)qg0 * HD + 16 * kc + 2 * tg;
        const float* p1 = Qh + (size_t)qg1 * HD + 16 * kc + 2 * tg;
        float2 v00 = *(const float2*)p0;
        float2 v01 = *(const float2*)(p0 + 8);
        float2 v10 = *(const float2*)p1;
        float2 v11 = *(const float2*)(p1 + 8);
        pack2(v00.x * 0.125f, v00.y * 0.125f, qfh[kc][0], qfl[kc][0]);
        pack2(v10.x * 0.125f, v10.y * 0.125f, qfh[kc][1], qfl[kc][1]);
        pack2(v01.x * 0.125f, v01.y * 0.125f, qfh[kc][2], qfl[kc][2]);
        pack2(v11.x * 0.125f, v11.y * 0.125f, qfh[kc][3], qfl[kc][3]);
    }

    float m0 = -1e30f, m1 = -1e30f, l0 = 0.f, l1 = 0.f;
    float accO[8][4];
#pragma unroll
    for (int nt = 0; nt < 8; nt++)
#pragma unroll
        for (int j = 0; j < 4; j++) accO[nt][j] = 0.f;

    const int ktmax = 2 * qt + 1;
    for (int kt = 0; kt <= ktmax; kt++) {
        const int k0 = kt * BKT;
        __syncthreads();   // prev tile's PV reads done before restaging

        // ---- stage K: Ks[d2][n] = pack(K[n][2d2], K[n][2d2+1]) -----------
#pragma unroll
        for (int it = 0; it < 8; it++) {
            const int idx = tid + it * 256;
            const int d2 = idx & 31, n = idx >> 5;
            float2 kv = *(const float2*)(Kh + (size_t)(k0 + n) * HD + 2 * d2);
            uint32_t hi, lo;
            pack2(kv.x, kv.y, hi, lo);
            smw[F_KHI + d2 * KSTR + n] = hi;
            smw[F_KLO + d2 * KSTR + n] = lo;
        }
        // ---- stage V: Vs[k2][d] = pack(V[2k2][d], V[2k2+1][d]) -----------
#pragma unroll
        for (int it = 0; it < 8; it++) {
            const int idx = tid + it * 256;
            const int d = idx & 63, k2 = idx >> 6;
            float v0 = Vh[(size_t)(k0 + 2 * k2) * HD + d];
            float v1 = Vh[(size_t)(k0 + 2 * k2 + 1) * HD + d];
            uint32_t hi, lo;
            pack2(v0, v1, hi, lo);
            smw[F_VHI + k2 * KSTR + d] = hi;
            smw[F_VLO + k2 * KSTR + d] = lo;
        }
        if (tid < 64) amsf[tid] = am[k0 + tid];
        __syncthreads();

        // ---- S = (Q/8) @ K^T  ->  s[8][4] fragments ----------------------
        float s[8][4];
#pragma unroll
        for (int nt = 0; nt < 8; nt++)
#pragma unroll
            for (int j = 0; j < 4; j++) s[nt][j] = 0.f;

#pragma unroll
        for (int kc = 0; kc < 4; kc++) {
#pragma unroll
            for (int nt = 0; nt < 8; nt++) {
                const int col = 8 * nt + g;
                const uint32_t bh0 = smw[F_KHI + (8 * kc + tg) * KSTR + col];
                const uint32_t bh1 = smw[F_KHI + (8 * kc + tg + 4) * KSTR + col];
                const uint32_t bl0 = smw[F_KLO + (8 * kc + tg) * KSTR + col];
                const uint32_t bl1 = smw[F_KLO + (8 * kc + tg + 4) * KSTR + col];
                MMA_BF16(s[nt], qfh[kc], bh0, bh1);
                MMA_BF16(s[nt], qfl[kc], bh0, bh1);
                MMA_BF16(s[nt], qfh[kc], bl0, bl1);
            }
        }

        // ---- causal mask + attention_mask --------------------------------
        const bool need_mask = (kt >= 2 * qt);
#pragma unroll
        for (int nt = 0; nt < 8; nt++) {
            const int kg = k0 + 8 * nt + 2 * tg;
            const float a0 = amsf[8 * nt + 2 * tg];
            const float a1 = amsf[8 * nt + 2 * tg + 1];
            if (need_mask) {
                s[nt][0] = (kg     <= qg0) ? s[nt][0] + a0 : MBIAS + a0;
                s[nt][1] = (kg + 1 <= qg0) ? s[nt][1] + a1 : MBIAS + a1;
                s[nt][2] = (kg     <= qg1) ? s[nt][2] + a0 : MBIAS + a0;
                s[nt][3] = (kg + 1 <= qg1) ? s[nt][3] + a1 : MBIAS + a1;
            } else {
                s[nt][0] += a0; s[nt][1] += a1;
                s[nt][2] += a0; s[nt][3] += a1;
            }
        }

        // ---- online softmax (2 rows per thread, quad-lane reduce) --------
        float t0 = -1e30f, t1 = -1e30f;
#pragma unroll
        for (int nt = 0; nt < 8; nt++) {
            t0 = fmaxf(t0, fmaxf(s[nt][0], s[nt][1]));
            t1 = fmaxf(t1, fmaxf(s[nt][2], s[nt][3]));
        }
#pragma unroll
        for (int off = 1; off <= 2; off <<= 1) {
            t0 = fmaxf(t0, __shfl_xor_sync(0xffffffffu, t0, off));
            t1 = fmaxf(t1, __shfl_xor_sync(0xffffffffu, t1, off));
        }
        const float mn0 = fmaxf(m0, t0), mn1 = fmaxf(m1, t1);
        const float corr0 = __expf(m0 - mn0), corr1 = __expf(m1 - mn1);
        m0 = mn0; m1 = mn1;

        float sum0 = 0.f, sum1 = 0.f;
#pragma unroll
        for (int nt = 0; nt < 8; nt++) {
            s[nt][0] = __expf(s[nt][0] - mn0);
            s[nt][1] = __expf(s[nt][1] - mn0);
            s[nt][2] = __expf(s[nt][2] - mn1);
            s[nt][3] = __expf(s[nt][3] - mn1);
            sum0 += s[nt][0] + s[nt][1];
            sum1 += s[nt][2] + s[nt][3];
        }
#pragma unroll
        for (int off = 1; off <= 2; off <<= 1) {
            sum0 += __shfl_xor_sync(0xffffffffu, sum0, off);
            sum1 += __shfl_xor_sync(0xffffffffu, sum1, off);
        }
        l0 = l0 * corr0 + sum0;
        l1 = l1 * corr1 + sum1;
#pragma unroll
        for (int nt = 0; nt < 8; nt++) {
            accO[nt][0] *= corr0; accO[nt][1] *= corr0;
            accO[nt][2] *= corr1; accO[nt][3] *= corr1;
        }

        // ---- P fragments (S C-frag layout == PV A-frag layout) -----------
        uint32_t ph[4][4], pl[4][4];
#pragma unroll
        for (int kc = 0; kc < 4; kc++) {
            pack2(s[2 * kc][0],     s[2 * kc][1],     ph[kc][0], pl[kc][0]);
            pack2(s[2 * kc][2],     s[2 * kc][3],     ph[kc][1], pl[kc][1]);
            pack2(s[2 * kc + 1][0], s[2 * kc + 1][1], ph[kc][2], pl[kc][2]);
            pack2(s[2 * kc + 1][2], s[2 * kc + 1][3], ph[kc][3], pl[kc][3]);
        }

        // ---- O += P @ V ---------------------------------------------------
#pragma unroll
        for (int kc = 0; kc < 4; kc++) {
#pragma unroll
            for (int nt = 0; nt < 8; nt++) {
                const int col = 8 * nt + g;
                const uint32_t vh0 = smw[F_VHI + (8 * kc + tg) * KSTR + col];
                const uint32_t vh1 = smw[F_VHI + (8 * kc + tg + 4) * KSTR + col];
                const uint32_t vl0 = smw[F_VLO + (8 * kc + tg) * KSTR + col];
                const uint32_t vl1 = smw[F_VLO + (8 * kc + tg + 4) * KSTR + col];
                MMA_BF16(accO[nt], ph[kc], vh0, vh1);
                MMA_BF16(accO[nt], pl[kc], vh0, vh1);
                MMA_BF16(accO[nt], ph[kc], vl0, vl1);
            }
        }
    }

    // ---- normalize + write merged [b, s2, h*64+d] -------------------------
    const float inv0 = 1.0f / l0, inv1 = 1.0f / l1;
    float* outp = g_att + (size_t)b * SEQ * NX + (size_t)h * HD;
#pragma unroll
    for (int nt = 0; nt < 8; nt++) {
        const int col = 8 * nt + 2 * tg;
        float2 o0, o1;
        o0.x = accO[nt][0] * inv0; o0.y = accO[nt][1] * inv0;
        o1.x = accO[nt][2] * inv1; o1.y = accO[nt][3] * inv1;
        *(float2*)(outp + (size_t)qg0 * NX + col) = o0;
        *(float2*)(outp + (size_t)qg1 * NX + col) = o1;
    }
}

// ---------------------------------------------------------------------------
extern "C" void kernel_launch(void* const* d_in, const int* in_sizes, int n_in,
                              void* d_out, int out_size)
{
    const float* hidden = (const float*)d_in[0];
    const float* amask  = (const float*)d_in[1];
    const float* w_attn = (const float*)d_in[2];
    const float* b_attn = (const float*)d_in[3];
    const float* w_proj = (const float*)d_in[4];
    const float* b_proj = (const float*)d_in[5];
    float* out = (float*)d_out;

    // 1) QKV projection (mma.sync bf16x3): split into g_q/g_k/g_v
    gemm_mma<<<dim3(3 * NX / TN, MROWS / TM), 256>>>(
        hidden, w_attn, b_attn, nullptr, 3 * NX, 1);

    // 2) Causal flash attention on tensor cores
    flash_mma<<<dim3(SEQ / BQ, NH, BSZ), 256>>>(amask);

    // 3) Output projection (mma.sync bf16x3): g_att @ w_proj + b -> d_out
    gemm_mma<<<dim3(NX / TN, MROWS / TM), 256>>>(
        nullptr, w_proj, b_proj, out, NX, 2);
}

// round 9
// speedup vs baseline: 2.7244x; 1.0818x over previous
#include <cuda_runtime.h>
#include <cuda_bf16.h>
#include <cstdint>

#define SEQ   2048
#define NX    768
#define NH    12
#define HD    64
#define BSZ   2
#define MROWS (BSZ*SEQ)
#define MBIAS -10000.0f

// ---------------- mma GEMM config ------------------------------------------
#define TM 128
#define TN 128
#define TK 32
#define NSTAGE (NX / TK)       // 24

#define ASTR 20                // A smem row stride (16 data + 4 pad words)
#define BSTR 136               // B smem k2 stride (128 data + 8 pad words)
#define SM_A_HI 0
#define SM_A_LO (128 * ASTR)                 // 2560
#define SM_B_HI (2 * 128 * ASTR)             // 5120
#define SM_B_LO (2 * 128 * ASTR + 16 * BSTR) // 7296
#define BUFW    (2 * 128 * ASTR + 2 * 16 * BSTR)  // 9472 words per buffer
#define GEMM_SMEM_BYTES (2 * BUFW * 4)            // 75776 B (double buffered)

// ---------------- flash config ---------------------------------------------
#define BQ 128
#define BKT 64
#define KSTR 68
#define F_KHI 0
#define F_KLO (32 * KSTR)
#define F_VHI (2 * 32 * KSTR)
#define F_VLO (3 * 32 * KSTR)
#define F_AMS (4 * 32 * KSTR)
#define FLASH_SMEM_WORDS (4 * 32 * KSTR + 64)

// ---------------- bf16 hi/lo scratch (allocation-free: __device__) ---------
// pre-paired words: low 16 bits = element 2j, high 16 = element 2j+1
#define PAIRS_H (MROWS * NX / 2)     // 1572864
__device__ __align__(16) uint32_t g_hh2[PAIRS_H],  g_hl2[PAIRS_H];   // hidden
__device__ __align__(16) uint32_t g_wah2[(NX/2)*3*NX], g_wal2[(NX/2)*3*NX];
__device__ __align__(16) uint32_t g_wph2[(NX/2)*NX],   g_wpl2[(NX/2)*NX];
__device__ __align__(16) uint32_t g_qh2[PAIRS_H],  g_ql2[PAIRS_H];   // pre-scaled 1/8
__device__ __align__(16) uint32_t g_kh2[PAIRS_H],  g_kl2[PAIRS_H];
__device__ __align__(16) uint32_t g_vh2[PAIRS_H],  g_vl2[PAIRS_H];
__device__ __align__(16) uint32_t g_ath2[PAIRS_H], g_atl2[PAIRS_H];  // attn out

// mma.sync m16n8k16 bf16 -> f32, D += A*B
#define MMA_BF16(d, a, b0, b1)                                              \
    asm volatile(                                                           \
        "mma.sync.aligned.m16n8k16.row.col.f32.bf16.bf16.f32 "              \
        "{%0,%1,%2,%3}, {%4,%5,%6,%7}, {%8,%9}, {%0,%1,%2,%3};"             \
        : "+f"((d)[0]), "+f"((d)[1]), "+f"((d)[2]), "+f"((d)[3])            \
        : "r"((a)[0]), "r"((a)[1]), "r"((a)[2]), "r"((a)[3]),               \
          "r"(b0), "r"(b1))

__device__ __forceinline__ void pack2(float x, float y,
                                      uint32_t& hi, uint32_t& lo) {
    __nv_bfloat16 hx = __float2bfloat16_rn(x);
    __nv_bfloat16 hy = __float2bfloat16_rn(y);
    __nv_bfloat16 lx = __float2bfloat16_rn(x - __bfloat162float(hx));
    __nv_bfloat16 ly = __float2bfloat16_rn(y - __bfloat162float(hy));
    hi = (uint32_t)__bfloat16_as_ushort(hx) | ((uint32_t)__bfloat16_as_ushort(hy) << 16);
    lo = (uint32_t)__bfloat16_as_ushort(lx) | ((uint32_t)__bfloat16_as_ushort(ly) << 16);
}

__device__ __forceinline__ uint32_t s2u(const void* p) {
    uint32_t a;
    asm("{ .reg .u64 t; cvta.to.shared.u64 t, %1; cvt.u32.u64 %0, t; }"
        : "=r"(a) : "l"(p));
    return a;
}
__device__ __forceinline__ void cp8(uint32_t s, const void* g) {
    asm volatile("cp.async.ca.shared.global [%0], [%1], 8;" :: "r"(s), "l"(g));
}
__device__ __forceinline__ void cp16(uint32_t s, const void* g) {
    asm volatile("cp.async.cg.shared.global [%0], [%1], 16;" :: "r"(s), "l"(g));
}
__device__ __forceinline__ void cpcommit() {
    asm volatile("cp.async.commit_group;" ::: "memory");
}
template<int N> __device__ __forceinline__ void cpwait() {
    asm volatile("cp.async.wait_group %0;" :: "n"(N) : "memory");
}

// ---------------------------------------------------------------------------
// Prep kernels: fp32 -> pre-paired bf16 hi/lo words
// ---------------------------------------------------------------------------
// pairs along contiguous (innermost) dim: h2[j] = pack(A[2j], A[2j+1])
__global__ void prep_row(const float* __restrict__ A,
                         uint32_t* __restrict__ h2, uint32_t* __restrict__ l2)
{
    const int i = blockIdx.x * 256 + threadIdx.x;
    float2 v = ((const float2*)A)[i];
    uint32_t h, l;
    pack2(v.x, v.y, h, l);
    h2[i] = h; l2[i] = l;
}
// pairs along k (rows): h2[k2*N+n] = pack(B[2k2][n], B[2k2+1][n])
__global__ void prep_colpair(const float* __restrict__ B,
                             uint32_t* __restrict__ h2, uint32_t* __restrict__ l2,
                             int N)
{
    const int n  = blockIdx.x * 256 + threadIdx.x;
    const int k2 = blockIdx.y;
    uint32_t h, l;
    pack2(B[(size_t)(2 * k2) * N + n], B[(size_t)(2 * k2 + 1) * N + n], h, l);
    h2[(size_t)k2 * N + n] = h;
    l2[(size_t)k2 * N + n] = l;
}

// ---------------------------------------------------------------------------
// Tensor-core GEMM on pre-packed bf16 operands, cp.async double buffered.
// C[4096, Ncols] = A[4096,768] @ B[768,Ncols] + bias  (bf16x3 emulation)
// mode 1: epilogue splits into q (scaled 1/8) / k / v bf16 hi/lo arrays
// mode 2: fp32 C output
// ---------------------------------------------------------------------------
__global__ __launch_bounds__(256, 2)
void gemm_mma(const uint32_t* __restrict__ a2h, const uint32_t* __restrict__ a2l,
              const uint32_t* __restrict__ b2h, const uint32_t* __restrict__ b2l,
              const float* __restrict__ bias, float* __restrict__ C,
              int Ncols, int mode)
{
    extern __shared__ __align__(16) uint32_t smw[];
    const uint32_t sbase = s2u(smw);

    const int tid  = threadIdx.x;
    const int lane = tid & 31, wid = tid >> 5;
    const int warp_m = wid >> 2;
    const int warp_n = wid & 3;
    const int m0 = blockIdx.y * TM;
    const int n0 = blockIdx.x * TN;
    const int g  = lane >> 2;
    const int tg = lane & 3;
    const int N2cols = Ncols;        // pair-array col count == Ncols
    const int AROWW = NX / 2;        // 384 words per A row

    float acc[4][4][4];
#pragma unroll
    for (int mt = 0; mt < 4; mt++)
#pragma unroll
        for (int nt = 0; nt < 4; nt++)
#pragma unroll
            for (int j = 0; j < 4; j++) acc[mt][nt][j] = 0.f;

    // stage s into buffer buf (pure async copies; operands pre-packed)
    auto stage = [&](int s, int buf) {
        const uint32_t so = (uint32_t)buf * BUFW;
        // A: 8-byte chunks, 1024 per array
#pragma unroll
        for (int it = 0; it < 4; it++) {
            const int c = tid + it * 256;
            const int row = c >> 3, k2e = (c & 7) * 2;
            const size_t go = (size_t)(m0 + row) * AROWW + s * 16 + k2e;
            const uint32_t sa = sbase + (so + SM_A_HI + row * ASTR + k2e) * 4;
            cp8(sa, a2h + go);
            cp8(sa + (SM_A_LO - SM_A_HI) * 4, a2l + go);
        }
        // B: 16-byte chunks, 512 per array
#pragma unroll
        for (int it = 0; it < 2; it++) {
            const int c = tid + it * 256;
            const int k2 = c >> 5, n4 = (c & 31) * 4;
            const size_t go = (size_t)(s * 16 + k2) * N2cols + n0 + n4;
            const uint32_t sa = sbase + (so + SM_B_HI + k2 * BSTR + n4) * 4;
            cp16(sa, b2h + go);
            cp16(sa + (SM_B_LO - SM_B_HI) * 4, b2l + go);
        }
        cpcommit();
    };

    stage(0, 0);
    for (int s = 0; s < NSTAGE; s++) {
        if (s + 1 < NSTAGE) { stage(s + 1, (s + 1) & 1); cpwait<1>(); }
        else                { cpwait<0>(); }
        __syncthreads();

        const uint32_t bo = (uint32_t)(s & 1) * BUFW;
#pragma unroll
        for (int c = 0; c < 2; c++) {
            uint32_t ah[4][4], al[4][4];
#pragma unroll
            for (int mt = 0; mt < 4; mt++) {
                const int r = warp_m * 64 + mt * 16 + g;
                const int base = bo + r * ASTR + c * 8 + tg;
                ah[mt][0] = smw[SM_A_HI + base];
                ah[mt][1] = smw[SM_A_HI + base + 8 * ASTR];
                ah[mt][2] = smw[SM_A_HI + base + 4];
                ah[mt][3] = smw[SM_A_HI + base + 8 * ASTR + 4];
                al[mt][0] = smw[SM_A_LO + base];
                al[mt][1] = smw[SM_A_LO + base + 8 * ASTR];
                al[mt][2] = smw[SM_A_LO + base + 4];
                al[mt][3] = smw[SM_A_LO + base + 8 * ASTR + 4];
            }
#pragma unroll
            for (int nt = 0; nt < 4; nt++) {
                const int ncol = warp_n * 32 + nt * 8 + g;
                const int kb = c * 8 + tg;
                const uint32_t bh0 = smw[bo + SM_B_HI + kb * BSTR + ncol];
                const uint32_t bh1 = smw[bo + SM_B_HI + (kb + 4) * BSTR + ncol];
                const uint32_t bl0 = smw[bo + SM_B_LO + kb * BSTR + ncol];
                const uint32_t bl1 = smw[bo + SM_B_LO + (kb + 4) * BSTR + ncol];
#pragma unroll
                for (int mt = 0; mt < 4; mt++) {
                    MMA_BF16(acc[mt][nt], ah[mt], bh0, bh1);
                    MMA_BF16(acc[mt][nt], al[mt], bh0, bh1);
                    MMA_BF16(acc[mt][nt], ah[mt], bl0, bl1);
                }
            }
        }
        __syncthreads();
    }

    // ---- epilogue ---------------------------------------------------------
    if (mode == 1) {
        const int which = n0 / NX;           // 0=Q, 1=K, 2=V (tile never spans)
        const int lcb = n0 - which * NX;
        uint32_t* dh = (which == 0) ? g_qh2 : (which == 1) ? g_kh2 : g_vh2;
        uint32_t* dl = (which == 0) ? g_ql2 : (which == 1) ? g_kl2 : g_vl2;
        const float sc = (which == 0) ? 0.125f : 1.0f;
#pragma unroll
        for (int mt = 0; mt < 4; mt++) {
            const int r0 = m0 + warp_m * 64 + mt * 16 + g;
#pragma unroll
            for (int nt = 0; nt < 4; nt++) {
                const int gc = n0 + warp_n * 32 + nt * 8 + tg * 2;
                const int lc = lcb + warp_n * 32 + nt * 8 + tg * 2;
                const float b0 = bias[gc], b1 = bias[gc + 1];
                uint32_t h, l;
                pack2((acc[mt][nt][0] + b0) * sc, (acc[mt][nt][1] + b1) * sc, h, l);
                dh[(size_t)r0 * 384 + lc / 2] = h;
                dl[(size_t)r0 * 384 + lc / 2] = l;
                pack2((acc[mt][nt][2] + b0) * sc, (acc[mt][nt][3] + b1) * sc, h, l);
                dh[(size_t)(r0 + 8) * 384 + lc / 2] = h;
                dl[(size_t)(r0 + 8) * 384 + lc / 2] = l;
            }
        }
    } else {
#pragma unroll
        for (int mt = 0; mt < 4; mt++) {
            const int r0 = m0 + warp_m * 64 + mt * 16 + g;
#pragma unroll
            for (int nt = 0; nt < 4; nt++) {
                const int gc = n0 + warp_n * 32 + nt * 8 + tg * 2;
                const float b0 = bias[gc], b1 = bias[gc + 1];
                float2 o0, o1;
                o0.x = acc[mt][nt][0] + b0; o0.y = acc[mt][nt][1] + b1;
                o1.x = acc[mt][nt][2] + b0; o1.y = acc[mt][nt][3] + b1;
                *(float2*)(C + (size_t)r0 * Ncols + gc)       = o0;
                *(float2*)(C + (size_t)(r0 + 8) * Ncols + gc) = o1;
            }
        }
    }
}

// ---------------------------------------------------------------------------
// Flash attention on mma.sync bf16x3, pre-packed bf16 Q/K/V inputs.
// ---------------------------------------------------------------------------
__global__ __launch_bounds__(256, 2)
void flash_mma(const float* __restrict__ am_g)
{
    __shared__ uint32_t smw[FLASH_SMEM_WORDS];
    float* amsf = (float*)(smw + F_AMS);

    const int tid = threadIdx.x;
    const int lane = tid & 31, wid = tid >> 5;
    const int g = lane >> 2, tg = lane & 3;
    const int qt = blockIdx.x, h = blockIdx.y, b = blockIdx.z;
    // per-head flat views (GPT-2 faithful reshape => head blocks contiguous)
    const size_t hoffw = (size_t)b * (SEQ * NX / 2) + (size_t)h * (SEQ * HD / 2);
    const uint32_t* Qh2 = g_qh2 + hoffw;
    const uint32_t* Ql2 = g_ql2 + hoffw;
    const uint32_t* Kh2 = g_kh2 + hoffw;
    const uint32_t* Kl2 = g_kl2 + hoffw;
    const uint16_t* Vh16 = (const uint16_t*)g_vh2 + 2 * hoffw;
    const uint16_t* Vl16 = (const uint16_t*)g_vl2 + 2 * hoffw;
    const float* am = am_g + (size_t)b * SEQ;
    const int q0 = qt * BQ;
    const int qg0 = q0 + wid * 16 + g;
    const int qg1 = qg0 + 8;

    // ---- Q fragments: direct pre-packed loads (already scaled by 1/8) -----
    uint32_t qfh[4][4], qfl[4][4];
#pragma unroll
    for (int kc = 0; kc < 4; kc++) {
        const size_t i0 = (size_t)qg0 * 32 + 8 * kc + tg;
        const size_t i1 = (size_t)qg1 * 32 + 8 * kc + tg;
        qfh[kc][0] = Qh2[i0];     qfl[kc][0] = Ql2[i0];
        qfh[kc][1] = Qh2[i1];     qfl[kc][1] = Ql2[i1];
        qfh[kc][2] = Qh2[i0 + 4]; qfl[kc][2] = Ql2[i0 + 4];
        qfh[kc][3] = Qh2[i1 + 4]; qfl[kc][3] = Ql2[i1 + 4];
    }

    float m0 = -1e30f, m1 = -1e30f, l0 = 0.f, l1 = 0.f;
    float accO[8][4];
#pragma unroll
    for (int nt = 0; nt < 8; nt++)
#pragma unroll
        for (int j = 0; j < 4; j++) accO[nt][j] = 0.f;

    const int ktmax = 2 * qt + 1;
    for (int kt = 0; kt <= ktmax; kt++) {
        const int k0 = kt * BKT;
        __syncthreads();

        // K: pre-paired along d — single word copies
#pragma unroll
        for (int it = 0; it < 8; it++) {
            const int idx = tid + it * 256;
            const int d2 = idx & 31, n = idx >> 5;
            const size_t go = (size_t)(k0 + n) * 32 + d2;
            smw[F_KHI + d2 * KSTR + n] = Kh2[go];
            smw[F_KLO + d2 * KSTR + n] = Kl2[go];
        }
        // V: pair across adjacent seq rows from u16 arrays
#pragma unroll
        for (int it = 0; it < 8; it++) {
            const int idx = tid + it * 256;
            const int d = idx & 63, k2 = idx >> 6;
            const size_t r0i = (size_t)(k0 + 2 * k2) * HD + d;
            smw[F_VHI + k2 * KSTR + d] =
                (uint32_t)Vh16[r0i] | ((uint32_t)Vh16[r0i + HD] << 16);
            smw[F_VLO + k2 * KSTR + d] =
                (uint32_t)Vl16[r0i] | ((uint32_t)Vl16[r0i + HD] << 16);
        }
        if (tid < 64) amsf[tid] = am[k0 + tid];
        __syncthreads();

        // ---- S = (Q/8) @ K^T ---------------------------------------------
        float s[8][4];
#pragma unroll
        for (int nt = 0; nt < 8; nt++)
#pragma unroll
            for (int j = 0; j < 4; j++) s[nt][j] = 0.f;

#pragma unroll
        for (int kc = 0; kc < 4; kc++) {
#pragma unroll
            for (int nt = 0; nt < 8; nt++) {
                const int col = 8 * nt + g;
                const uint32_t bh0 = smw[F_KHI + (8 * kc + tg) * KSTR + col];
                const uint32_t bh1 = smw[F_KHI + (8 * kc + tg + 4) * KSTR + col];
                const uint32_t bl0 = smw[F_KLO + (8 * kc + tg) * KSTR + col];
                const uint32_t bl1 = smw[F_KLO + (8 * kc + tg + 4) * KSTR + col];
                MMA_BF16(s[nt], qfh[kc], bh0, bh1);
                MMA_BF16(s[nt], qfl[kc], bh0, bh1);
                MMA_BF16(s[nt], qfh[kc], bl0, bl1);
            }
        }

        // ---- mask + attention_mask ---------------------------------------
        const bool need_mask = (kt >= 2 * qt);
#pragma unroll
        for (int nt = 0; nt < 8; nt++) {
            const int kg = k0 + 8 * nt + 2 * tg;
            const float a0 = amsf[8 * nt + 2 * tg];
            const float a1 = amsf[8 * nt + 2 * tg + 1];
            if (need_mask) {
                s[nt][0] = (kg     <= qg0) ? s[nt][0] + a0 : MBIAS + a0;
                s[nt][1] = (kg + 1 <= qg0) ? s[nt][1] + a1 : MBIAS + a1;
                s[nt][2] = (kg     <= qg1) ? s[nt][2] + a0 : MBIAS + a0;
                s[nt][3] = (kg + 1 <= qg1) ? s[nt][3] + a1 : MBIAS + a1;
            } else {
                s[nt][0] += a0; s[nt][1] += a1;
                s[nt][2] += a0; s[nt][3] += a1;
            }
        }

        // ---- online softmax ----------------------------------------------
        float t0 = -1e30f, t1 = -1e30f;
#pragma unroll
        for (int nt = 0; nt < 8; nt++) {
            t0 = fmaxf(t0, fmaxf(s[nt][0], s[nt][1]));
            t1 = fmaxf(t1, fmaxf(s[nt][2], s[nt][3]));
        }
#pragma unroll
        for (int off = 1; off <= 2; off <<= 1) {
            t0 = fmaxf(t0, __shfl_xor_sync(0xffffffffu, t0, off));
            t1 = fmaxf(t1, __shfl_xor_sync(0xffffffffu, t1, off));
        }
        const float mn0 = fmaxf(m0, t0), mn1 = fmaxf(m1, t1);
        const float corr0 = __expf(m0 - mn0), corr1 = __expf(m1 - mn1);
        m0 = mn0; m1 = mn1;

        float sum0 = 0.f, sum1 = 0.f;
#pragma unroll
        for (int nt = 0; nt < 8; nt++) {
            s[nt][0] = __expf(s[nt][0] - mn0);
            s[nt][1] = __expf(s[nt][1] - mn0);
            s[nt][2] = __expf(s[nt][2] - mn1);
            s[nt][3] = __expf(s[nt][3] - mn1);
            sum0 += s[nt][0] + s[nt][1];
            sum1 += s[nt][2] + s[nt][3];
        }
#pragma unroll
        for (int off = 1; off <= 2; off <<= 1) {
            sum0 += __shfl_xor_sync(0xffffffffu, sum0, off);
            sum1 += __shfl_xor_sync(0xffffffffu, sum1, off);
        }
        l0 = l0 * corr0 + sum0;
        l1 = l1 * corr1 + sum1;
#pragma unroll
        for (int nt = 0; nt < 8; nt++) {
            accO[nt][0] *= corr0; accO[nt][1] *= corr0;
            accO[nt][2] *= corr1; accO[nt][3] *= corr1;
        }

        // ---- P fragments (register-only convert) -------------------------
        uint32_t ph[4][4], pl[4][4];
#pragma unroll
        for (int kc = 0; kc < 4; kc++) {
            pack2(s[2 * kc][0],     s[2 * kc][1],     ph[kc][0], pl[kc][0]);
            pack2(s[2 * kc][2],     s[2 * kc][3],     ph[kc][1], pl[kc][1]);
            pack2(s[2 * kc + 1][0], s[2 * kc + 1][1], ph[kc][2], pl[kc][2]);
            pack2(s[2 * kc + 1][2], s[2 * kc + 1][3], ph[kc][3], pl[kc][3]);
        }

        // ---- O += P @ V ---------------------------------------------------
#pragma unroll
        for (int kc = 0; kc < 4; kc++) {
#pragma unroll
            for (int nt = 0; nt < 8; nt++) {
                const int col = 8 * nt + g;
                const uint32_t vh0 = smw[F_VHI + (8 * kc + tg) * KSTR + col];
                const uint32_t vh1 = smw[F_VHI + (8 * kc + tg + 4) * KSTR + col];
                const uint32_t vl0 = smw[F_VLO + (8 * kc + tg) * KSTR + col];
                const uint32_t vl1 = smw[F_VLO + (8 * kc + tg + 4) * KSTR + col];
                MMA_BF16(accO[nt], ph[kc], vh0, vh1);
                MMA_BF16(accO[nt], pl[kc], vh0, vh1);
                MMA_BF16(accO[nt], ph[kc], vl0, vl1);
            }
        }
    }

    // ---- normalize, split to bf16 hi/lo, write merged layout -------------
    const float inv0 = 1.0f / l0, inv1 = 1.0f / l1;
    const size_t rb = (size_t)b * SEQ;
#pragma unroll
    for (int nt = 0; nt < 8; nt++) {
        const int col = h * HD + 8 * nt + 2 * tg;
        uint32_t hh, ll;
        pack2(accO[nt][0] * inv0, accO[nt][1] * inv0, hh, ll);
        g_ath2[(rb + qg0) * 384 + col / 2] = hh;
        g_atl2[(rb + qg0) * 384 + col / 2] = ll;
        pack2(accO[nt][2] * inv1, accO[nt][3] * inv1, hh, ll);
        g_ath2[(rb + qg1) * 384 + col / 2] = hh;
        g_atl2[(rb + qg1) * 384 + col / 2] = ll;
    }
}

// ---------------------------------------------------------------------------
extern "C" void kernel_launch(void* const* d_in, const int* in_sizes, int n_in,
                              void* d_out, int out_size)
{
    const float* hidden = (const float*)d_in[0];
    const float* amask  = (const float*)d_in[1];
    const float* w_attn = (const float*)d_in[2];
    const float* b_attn = (const float*)d_in[3];
    const float* w_proj = (const float*)d_in[4];
    const float* b_proj = (const float*)d_in[5];
    float* out = (float*)d_out;

    cudaFuncSetAttribute(gemm_mma,
        cudaFuncAttributeMaxDynamicSharedMemorySize, GEMM_SMEM_BYTES);

    uint32_t *hh2, *hl2, *wah2, *wal2, *wph2, *wpl2;
    uint32_t *ath2, *atl2;
    cudaGetSymbolAddress((void**)&hh2,  g_hh2);
    cudaGetSymbolAddress((void**)&hl2,  g_hl2);
    cudaGetSymbolAddress((void**)&wah2, g_wah2);
    cudaGetSymbolAddress((void**)&wal2, g_wal2);
    cudaGetSymbolAddress((void**)&wph2, g_wph2);
    cudaGetSymbolAddress((void**)&wpl2, g_wpl2);
    cudaGetSymbolAddress((void**)&ath2, g_ath2);
    cudaGetSymbolAddress((void**)&atl2, g_atl2);

    // 0) precompute bf16 hi/lo pair-packed operands
    prep_row<<<PAIRS_H / 256, 256>>>(hidden, hh2, hl2);
    prep_colpair<<<dim3(3 * NX / 256, NX / 2), 256>>>(w_attn, wah2, wal2, 3 * NX);
    prep_colpair<<<dim3(NX / 256, NX / 2), 256>>>(w_proj, wph2, wpl2, NX);

    // 1) QKV projection -> q (scaled) / k / v bf16 hi/lo
    gemm_mma<<<dim3(3 * NX / TN, MROWS / TM), 256, GEMM_SMEM_BYTES>>>(
        hh2, hl2, wah2, wal2, b_attn, nullptr, 3 * NX, 1);

    // 2) Causal flash attention on tensor cores -> attn out bf16 hi/lo
    flash_mma<<<dim3(SEQ / BQ, NH, BSZ), 256>>>(amask);

    // 3) Output projection -> fp32 out
    gemm_mma<<<dim3(NX / TN, MROWS / TM), 256, GEMM_SMEM_BYTES>>>(
        ath2, atl2, wph2, wpl2, b_proj, out, NX, 2);
}

// round 10
// speedup vs baseline: 3.1187x; 1.1447x over previous
#include <cuda_runtime.h>
#include <cuda_bf16.h>
#include <cstdint>

#define SEQ   2048
#define NX    768
#define NH    12
#define HD    64
#define BSZ   2
#define MROWS (BSZ*SEQ)
#define MBIAS -10000.0f

// ---------------- mma GEMM config ------------------------------------------
#define TM 128
#define TN 128
#define TK 32
#define NSTAGE (NX / TK)       // 24

#define ASTR 20
#define BSTR 136
#define SM_A_HI 0
#define SM_A_LO (128 * ASTR)
#define SM_B_HI (2 * 128 * ASTR)
#define SM_B_LO (2 * 128 * ASTR + 16 * BSTR)
#define BUFW    (2 * 128 * ASTR + 2 * 16 * BSTR)
#define GEMM_SMEM_BYTES (2 * BUFW * 4)

// ---------------- flash config (double-buffered cp.async) ------------------
#define BQ 128
#define BKT 64
// per-buffer word offsets: K [n][36] (64x36=2304), V [k2][68] (32x68=2176)
#define F_KHI 0
#define F_KLO 2304
#define F_VHI 4608
#define F_VLO 6784
#define F_AM  8960
#define FBUFW 9024
#define FLASH_SMEM_BYTES (2 * FBUFW * 4)   // 72192

// ---------------- bf16 hi/lo scratch (allocation-free: __device__) ---------
#define PAIRS_H (MROWS * NX / 2)
__device__ __align__(16) uint32_t g_hh2[PAIRS_H],  g_hl2[PAIRS_H];
__device__ __align__(16) uint32_t g_wah2[(NX/2)*3*NX], g_wal2[(NX/2)*3*NX];
__device__ __align__(16) uint32_t g_wph2[(NX/2)*NX],   g_wpl2[(NX/2)*NX];
__device__ __align__(16) uint32_t g_qh2[PAIRS_H],  g_ql2[PAIRS_H];   // 1/8 scaled
__device__ __align__(16) uint32_t g_kh2[PAIRS_H],  g_kl2[PAIRS_H];
__device__ __align__(16) uint32_t g_vh2[PAIRS_H],  g_vl2[PAIRS_H];
__device__ __align__(16) uint32_t g_vph2[PAIRS_H], g_vpl2[PAIRS_H]; // row-paired V
__device__ __align__(16) uint32_t g_ath2[PAIRS_H], g_atl2[PAIRS_H];

#define MMA_BF16(d, a, b0, b1)                                              \
    asm volatile(                                                           \
        "mma.sync.aligned.m16n8k16.row.col.f32.bf16.bf16.f32 "              \
        "{%0,%1,%2,%3}, {%4,%5,%6,%7}, {%8,%9}, {%0,%1,%2,%3};"             \
        : "+f"((d)[0]), "+f"((d)[1]), "+f"((d)[2]), "+f"((d)[3])            \
        : "r"((a)[0]), "r"((a)[1]), "r"((a)[2]), "r"((a)[3]),               \
          "r"(b0), "r"(b1))

__device__ __forceinline__ void pack2(float x, float y,
                                      uint32_t& hi, uint32_t& lo) {
    __nv_bfloat16 hx = __float2bfloat16_rn(x);
    __nv_bfloat16 hy = __float2bfloat16_rn(y);
    __nv_bfloat16 lx = __float2bfloat16_rn(x - __bfloat162float(hx));
    __nv_bfloat16 ly = __float2bfloat16_rn(y - __bfloat162float(hy));
    hi = (uint32_t)__bfloat16_as_ushort(hx) | ((uint32_t)__bfloat16_as_ushort(hy) << 16);
    lo = (uint32_t)__bfloat16_as_ushort(lx) | ((uint32_t)__bfloat16_as_ushort(ly) << 16);
}

__device__ __forceinline__ uint32_t s2u(const void* p) {
    uint32_t a;
    asm("{ .reg .u64 t; cvta.to.shared.u64 t, %1; cvt.u32.u64 %0, t; }"
        : "=r"(a) : "l"(p));
    return a;
}
__device__ __forceinline__ void cp8(uint32_t s, const void* g) {
    asm volatile("cp.async.ca.shared.global [%0], [%1], 8;" :: "r"(s), "l"(g));
}
__device__ __forceinline__ void cp16(uint32_t s, const void* g) {
    asm volatile("cp.async.cg.shared.global [%0], [%1], 16;" :: "r"(s), "l"(g));
}
__device__ __forceinline__ void cpcommit() {
    asm volatile("cp.async.commit_group;" ::: "memory");
}
template<int N> __device__ __forceinline__ void cpwait() {
    asm volatile("cp.async.wait_group %0;" :: "n"(N) : "memory");
}

// ---------------------------------------------------------------------------
// Prep kernels
// ---------------------------------------------------------------------------
__global__ void prep_row(const float* __restrict__ A,
                         uint32_t* __restrict__ h2, uint32_t* __restrict__ l2)
{
    const int i = blockIdx.x * 256 + threadIdx.x;
    float2 v = ((const float2*)A)[i];
    uint32_t h, l;
    pack2(v.x, v.y, h, l);
    h2[i] = h; l2[i] = l;
}
__global__ void prep_colpair(const float* __restrict__ B,
                             uint32_t* __restrict__ h2, uint32_t* __restrict__ l2,
                             int N)
{
    const int n  = blockIdx.x * 256 + threadIdx.x;
    const int k2 = blockIdx.y;
    uint32_t h, l;
    pack2(B[(size_t)(2 * k2) * N + n], B[(size_t)(2 * k2 + 1) * N + n], h, l);
    h2[(size_t)k2 * N + n] = h;
    l2[(size_t)k2 * N + n] = l;
}
// V repack: per head, pair adjacent seq rows -> [k2][d] word arrays
__global__ void repack_v()
{
    const int i = blockIdx.x * 256 + threadIdx.x;     // over PAIRS_H words
    const int head = i >> 16;                          // / (1024*64)
    const int rem  = i & 65535;
    const int k2 = rem >> 6, d = rem & 63;
    const uint16_t* vh = (const uint16_t*)g_vh2;
    const uint16_t* vl = (const uint16_t*)g_vl2;
    const size_t s0 = (size_t)head * SEQ * HD + (size_t)(2 * k2) * HD + d;
    g_vph2[i] = (uint32_t)vh[s0] | ((uint32_t)vh[s0 + HD] << 16);
    g_vpl2[i] = (uint32_t)vl[s0] | ((uint32_t)vl[s0 + HD] << 16);
}

// ---------------------------------------------------------------------------
// Tensor-core GEMM (unchanged from passing R9)
// ---------------------------------------------------------------------------
__global__ __launch_bounds__(256, 2)
void gemm_mma(const uint32_t* __restrict__ a2h, const uint32_t* __restrict__ a2l,
              const uint32_t* __restrict__ b2h, const uint32_t* __restrict__ b2l,
              const float* __restrict__ bias, float* __restrict__ C,
              int Ncols, int mode)
{
    extern __shared__ __align__(16) uint32_t smw[];
    const uint32_t sbase = s2u(smw);

    const int tid  = threadIdx.x;
    const int lane = tid & 31, wid = tid >> 5;
    const int warp_m = wid >> 2;
    const int warp_n = wid & 3;
    const int m0 = blockIdx.y * TM;
    const int n0 = blockIdx.x * TN;
    const int g  = lane >> 2;
    const int tg = lane & 3;
    const int AROWW = NX / 2;

    float acc[4][4][4];
#pragma unroll
    for (int mt = 0; mt < 4; mt++)
#pragma unroll
        for (int nt = 0; nt < 4; nt++)
#pragma unroll
            for (int j = 0; j < 4; j++) acc[mt][nt][j] = 0.f;

    auto stage = [&](int s, int buf) {
        const uint32_t so = (uint32_t)buf * BUFW;
#pragma unroll
        for (int it = 0; it < 4; it++) {
            const int c = tid + it * 256;
            const int row = c >> 3, k2e = (c & 7) * 2;
            const size_t go = (size_t)(m0 + row) * AROWW + s * 16 + k2e;
            const uint32_t sa = sbase + (so + SM_A_HI + row * ASTR + k2e) * 4;
            cp8(sa, a2h + go);
            cp8(sa + (SM_A_LO - SM_A_HI) * 4, a2l + go);
        }
#pragma unroll
        for (int it = 0; it < 2; it++) {
            const int c = tid + it * 256;
            const int k2 = c >> 5, n4 = (c & 31) * 4;
            const size_t go = (size_t)(s * 16 + k2) * Ncols + n0 + n4;
            const uint32_t sa = sbase + (so + SM_B_HI + k2 * BSTR + n4) * 4;
            cp16(sa, b2h + go);
            cp16(sa + (SM_B_LO - SM_B_HI) * 4, b2l + go);
        }
        cpcommit();
    };

    stage(0, 0);
    for (int s = 0; s < NSTAGE; s++) {
        if (s + 1 < NSTAGE) { stage(s + 1, (s + 1) & 1); cpwait<1>(); }
        else                { cpwait<0>(); }
        __syncthreads();

        const uint32_t bo = (uint32_t)(s & 1) * BUFW;
#pragma unroll
        for (int c = 0; c < 2; c++) {
            uint32_t ah[4][4], al[4][4];
#pragma unroll
            for (int mt = 0; mt < 4; mt++) {
                const int r = warp_m * 64 + mt * 16 + g;
                const int base = bo + r * ASTR + c * 8 + tg;
                ah[mt][0] = smw[SM_A_HI + base];
                ah[mt][1] = smw[SM_A_HI + base + 8 * ASTR];
                ah[mt][2] = smw[SM_A_HI + base + 4];
                ah[mt][3] = smw[SM_A_HI + base + 8 * ASTR + 4];
                al[mt][0] = smw[SM_A_LO + base];
                al[mt][1] = smw[SM_A_LO + base + 8 * ASTR];
                al[mt][2] = smw[SM_A_LO + base + 4];
                al[mt][3] = smw[SM_A_LO + base + 8 * ASTR + 4];
            }
#pragma unroll
            for (int nt = 0; nt < 4; nt++) {
                const int ncol = warp_n * 32 + nt * 8 + g;
                const int kb = c * 8 + tg;
                const uint32_t bh0 = smw[bo + SM_B_HI + kb * BSTR + ncol];
                const uint32_t bh1 = smw[bo + SM_B_HI + (kb + 4) * BSTR + ncol];
                const uint32_t bl0 = smw[bo + SM_B_LO + kb * BSTR + ncol];
                const uint32_t bl1 = smw[bo + SM_B_LO + (kb + 4) * BSTR + ncol];
#pragma unroll
                for (int mt = 0; mt < 4; mt++) {
                    MMA_BF16(acc[mt][nt], ah[mt], bh0, bh1);
                    MMA_BF16(acc[mt][nt], al[mt], bh0, bh1);
                    MMA_BF16(acc[mt][nt], ah[mt], bl0, bl1);
                }
            }
        }
        __syncthreads();
    }

    if (mode == 1) {
        const int which = n0 / NX;
        const int lcb = n0 - which * NX;
        uint32_t* dh = (which == 0) ? g_qh2 : (which == 1) ? g_kh2 : g_vh2;
        uint32_t* dl = (which == 0) ? g_ql2 : (which == 1) ? g_kl2 : g_vl2;
        const float sc = (which == 0) ? 0.125f : 1.0f;
#pragma unroll
        for (int mt = 0; mt < 4; mt++) {
            const int r0 = m0 + warp_m * 64 + mt * 16 + g;
#pragma unroll
            for (int nt = 0; nt < 4; nt++) {
                const int gc = n0 + warp_n * 32 + nt * 8 + tg * 2;
                const int lc = lcb + warp_n * 32 + nt * 8 + tg * 2;
                const float b0 = bias[gc], b1 = bias[gc + 1];
                uint32_t h, l;
                pack2((acc[mt][nt][0] + b0) * sc, (acc[mt][nt][1] + b1) * sc, h, l);
                dh[(size_t)r0 * 384 + lc / 2] = h;
                dl[(size_t)r0 * 384 + lc / 2] = l;
                pack2((acc[mt][nt][2] + b0) * sc, (acc[mt][nt][3] + b1) * sc, h, l);
                dh[(size_t)(r0 + 8) * 384 + lc / 2] = h;
                dl[(size_t)(r0 + 8) * 384 + lc / 2] = l;
            }
        }
    } else {
#pragma unroll
        for (int mt = 0; mt < 4; mt++) {
            const int r0 = m0 + warp_m * 64 + mt * 16 + g;
#pragma unroll
            for (int nt = 0; nt < 4; nt++) {
                const int gc = n0 + warp_n * 32 + nt * 8 + tg * 2;
                const float b0 = bias[gc], b1 = bias[gc + 1];
                float2 o0, o1;
                o0.x = acc[mt][nt][0] + b0; o0.y = acc[mt][nt][1] + b1;
                o1.x = acc[mt][nt][2] + b0; o1.y = acc[mt][nt][3] + b1;
                *(float2*)(C + (size_t)r0 * Ncols + gc)       = o0;
                *(float2*)(C + (size_t)(r0 + 8) * Ncols + gc) = o1;
            }
        }
    }
}

// ---------------------------------------------------------------------------
// Flash attention: cp.async double-buffered K/V staging, longest-first qt.
// K smem [n][36] (frag bank = 4g+tg), V smem [k2][68] (frag bank = 4tg+g).
// ---------------------------------------------------------------------------
__global__ __launch_bounds__(256, 2)
void flash_mma(const float* __restrict__ am_g)
{
    extern __shared__ __align__(16) uint32_t smw[];
    const uint32_t sbase = s2u(smw);

    const int tid = threadIdx.x;
    const int lane = tid & 31, wid = tid >> 5;
    const int g = lane >> 2, tg = lane & 3;
    const int qt = (SEQ / BQ - 1) - blockIdx.x;       // longest first
    const int h = blockIdx.y, b = blockIdx.z;
    const size_t hoffw = (size_t)b * (SEQ * NX / 2) + (size_t)h * (SEQ * HD / 2);
    const uint32_t* Qh2 = g_qh2 + hoffw;
    const uint32_t* Ql2 = g_ql2 + hoffw;
    const uint32_t* Kh2 = g_kh2 + hoffw;
    const uint32_t* Kl2 = g_kl2 + hoffw;
    const uint32_t* Vph = g_vph2 + hoffw;
    const uint32_t* Vpl = g_vpl2 + hoffw;
    const float* am = am_g + (size_t)b * SEQ;
    const int q0 = qt * BQ;
    const int qg0 = q0 + wid * 16 + g;
    const int qg1 = qg0 + 8;

    // Q fragments (pre-scaled, pre-packed)
    uint32_t qfh[4][4], qfl[4][4];
#pragma unroll
    for (int kc = 0; kc < 4; kc++) {
        const size_t i0 = (size_t)qg0 * 32 + 8 * kc + tg;
        const size_t i1 = (size_t)qg1 * 32 + 8 * kc + tg;
        qfh[kc][0] = Qh2[i0];     qfl[kc][0] = Ql2[i0];
        qfh[kc][1] = Qh2[i1];     qfl[kc][1] = Ql2[i1];
        qfh[kc][2] = Qh2[i0 + 4]; qfl[kc][2] = Ql2[i0 + 4];
        qfh[kc][3] = Qh2[i1 + 4]; qfl[kc][3] = Ql2[i1 + 4];
    }

    float m0 = -1e30f, m1 = -1e30f, l0 = 0.f, l1 = 0.f;
    float accO[8][4];
#pragma unroll
    for (int nt = 0; nt < 8; nt++)
#pragma unroll
        for (int j = 0; j < 4; j++) accO[nt][j] = 0.f;

    // pure-copy cp.async staging of tile kt into buffer buf
    auto stageF = [&](int kt, int buf) {
        const int k0 = kt * BKT;
        const uint32_t so = sbase + (uint32_t)buf * (FBUFW * 4);
#pragma unroll
        for (int it = 0; it < 2; it++) {            // K: 512 cp16 per array
            const int c = tid + it * 256;
            const int n = c >> 3, q4 = (c & 7) * 4;
            const size_t go = (size_t)(k0 + n) * 32 + q4;
            cp16(so + (F_KHI + n * 36 + q4) * 4, Kh2 + go);
            cp16(so + (F_KLO + n * 36 + q4) * 4, Kl2 + go);
        }
#pragma unroll
        for (int it = 0; it < 2; it++) {            // V: 512 cp16 per array
            const int c = tid + it * 256;
            const int k2 = c >> 4, d4 = (c & 15) * 4;
            const size_t go = (size_t)(k0 / 2 + k2) * 64 + d4;
            cp16(so + (F_VHI + k2 * 68 + d4) * 4, Vph + go);
            cp16(so + (F_VLO + k2 * 68 + d4) * 4, Vpl + go);
        }
        if (tid < 16) cp16(so + (F_AM + tid * 4) * 4, am + k0 + tid * 4);
        cpcommit();
    };

    const int ktmax = 2 * qt + 1;
    stageF(0, 0);
    for (int kt = 0; kt <= ktmax; kt++) {
        cpwait<0>();
        __syncthreads();
        if (kt < ktmax) stageF(kt + 1, (kt + 1) & 1);

        const uint32_t* bp = smw + (uint32_t)(kt & 1) * FBUFW;
        const float* amf = (const float*)(bp + F_AM);
        const int k0 = kt * BKT;

        // ---- S = (Q/8) @ K^T ---------------------------------------------
        float s[8][4];
#pragma unroll
        for (int nt = 0; nt < 8; nt++)
#pragma unroll
            for (int j = 0; j < 4; j++) s[nt][j] = 0.f;

#pragma unroll
        for (int kc = 0; kc < 4; kc++) {
#pragma unroll
            for (int nt = 0; nt < 8; nt++) {
                const int cw = (8 * nt + g) * 36 + 8 * kc + tg;
                const uint32_t bh0 = bp[F_KHI + cw];
                const uint32_t bh1 = bp[F_KHI + cw + 4];
                const uint32_t bl0 = bp[F_KLO + cw];
                const uint32_t bl1 = bp[F_KLO + cw + 4];
                MMA_BF16(s[nt], qfh[kc], bh0, bh1);
                MMA_BF16(s[nt], qfl[kc], bh0, bh1);
                MMA_BF16(s[nt], qfh[kc], bl0, bl1);
            }
        }

        // ---- mask + attention_mask ---------------------------------------
        const bool need_mask = (kt >= 2 * qt);
#pragma unroll
        for (int nt = 0; nt < 8; nt++) {
            const int kg = k0 + 8 * nt + 2 * tg;
            const float a0 = amf[8 * nt + 2 * tg];
            const float a1 = amf[8 * nt + 2 * tg + 1];
            if (need_mask) {
                s[nt][0] = (kg     <= qg0) ? s[nt][0] + a0 : MBIAS + a0;
                s[nt][1] = (kg + 1 <= qg0) ? s[nt][1] + a1 : MBIAS + a1;
                s[nt][2] = (kg     <= qg1) ? s[nt][2] + a0 : MBIAS + a0;
                s[nt][3] = (kg + 1 <= qg1) ? s[nt][3] + a1 : MBIAS + a1;
            } else {
                s[nt][0] += a0; s[nt][1] += a1;
                s[nt][2] += a0; s[nt][3] += a1;
            }
        }

        // ---- online softmax ----------------------------------------------
        float t0 = -1e30f, t1 = -1e30f;
#pragma unroll
        for (int nt = 0; nt < 8; nt++) {
            t0 = fmaxf(t0, fmaxf(s[nt][0], s[nt][1]));
            t1 = fmaxf(t1, fmaxf(s[nt][2], s[nt][3]));
        }
#pragma unroll
        for (int off = 1; off <= 2; off <<= 1) {
            t0 = fmaxf(t0, __shfl_xor_sync(0xffffffffu, t0, off));
            t1 = fmaxf(t1, __shfl_xor_sync(0xffffffffu, t1, off));
        }
        const float mn0 = fmaxf(m0, t0), mn1 = fmaxf(m1, t1);
        const float corr0 = __expf(m0 - mn0), corr1 = __expf(m1 - mn1);
        m0 = mn0; m1 = mn1;

        float sum0 = 0.f, sum1 = 0.f;
#pragma unroll
        for (int nt = 0; nt < 8; nt++) {
            s[nt][0] = __expf(s[nt][0] - mn0);
            s[nt][1] = __expf(s[nt][1] - mn0);
            s[nt][2] = __expf(s[nt][2] - mn1);
            s[nt][3] = __expf(s[nt][3] - mn1);
            sum0 += s[nt][0] + s[nt][1];
            sum1 += s[nt][2] + s[nt][3];
        }
#pragma unroll
        for (int off = 1; off <= 2; off <<= 1) {
            sum0 += __shfl_xor_sync(0xffffffffu, sum0, off);
            sum1 += __shfl_xor_sync(0xffffffffu, sum1, off);
        }
        l0 = l0 * corr0 + sum0;
        l1 = l1 * corr1 + sum1;
#pragma unroll
        for (int nt = 0; nt < 8; nt++) {
            accO[nt][0] *= corr0; accO[nt][1] *= corr0;
            accO[nt][2] *= corr1; accO[nt][3] *= corr1;
        }

        // ---- P fragments --------------------------------------------------
        uint32_t ph[4][4], pl[4][4];
#pragma unroll
        for (int kc = 0; kc < 4; kc++) {
            pack2(s[2 * kc][0],     s[2 * kc][1],     ph[kc][0], pl[kc][0]);
            pack2(s[2 * kc][2],     s[2 * kc][3],     ph[kc][1], pl[kc][1]);
            pack2(s[2 * kc + 1][0], s[2 * kc + 1][1], ph[kc][2], pl[kc][2]);
            pack2(s[2 * kc + 1][2], s[2 * kc + 1][3], ph[kc][3], pl[kc][3]);
        }

        // ---- O += P @ V ---------------------------------------------------
#pragma unroll
        for (int kc = 0; kc < 4; kc++) {
#pragma unroll
            for (int nt = 0; nt < 8; nt++) {
                const int col = 8 * nt + g;
                const uint32_t vh0 = bp[F_VHI + (8 * kc + tg) * 68 + col];
                const uint32_t vh1 = bp[F_VHI + (8 * kc + tg + 4) * 68 + col];
                const uint32_t vl0 = bp[F_VLO + (8 * kc + tg) * 68 + col];
                const uint32_t vl1 = bp[F_VLO + (8 * kc + tg + 4) * 68 + col];
                MMA_BF16(accO[nt], ph[kc], vh0, vh1);
                MMA_BF16(accO[nt], pl[kc], vh0, vh1);
                MMA_BF16(accO[nt], ph[kc], vl0, vl1);
            }
        }
    }

    // ---- normalize + write bf16 hi/lo merged layout -----------------------
    const float inv0 = 1.0f / l0, inv1 = 1.0f / l1;
    const size_t rb = (size_t)b * SEQ;
#pragma unroll
    for (int nt = 0; nt < 8; nt++) {
        const int col = h * HD + 8 * nt + 2 * tg;
        uint32_t hh, ll;
        pack2(accO[nt][0] * inv0, accO[nt][1] * inv0, hh, ll);
        g_ath2[(rb + qg0) * 384 + col / 2] = hh;
        g_atl2[(rb + qg0) * 384 + col / 2] = ll;
        pack2(accO[nt][2] * inv1, accO[nt][3] * inv1, hh, ll);
        g_ath2[(rb + qg1) * 384 + col / 2] = hh;
        g_atl2[(rb + qg1) * 384 + col / 2] = ll;
    }
}

// ---------------------------------------------------------------------------
extern "C" void kernel_launch(void* const* d_in, const int* in_sizes, int n_in,
                              void* d_out, int out_size)
{
    const float* hidden = (const float*)d_in[0];
    const float* amask  = (const float*)d_in[1];
    const float* w_attn = (const float*)d_in[2];
    const float* b_attn = (const float*)d_in[3];
    const float* w_proj = (const float*)d_in[4];
    const float* b_proj = (const float*)d_in[5];
    float* out = (float*)d_out;

    cudaFuncSetAttribute(gemm_mma,
        cudaFuncAttributeMaxDynamicSharedMemorySize, GEMM_SMEM_BYTES);
    cudaFuncSetAttribute(flash_mma,
        cudaFuncAttributeMaxDynamicSharedMemorySize, FLASH_SMEM_BYTES);

    uint32_t *hh2, *hl2, *wah2, *wal2, *wph2, *wpl2, *ath2, *atl2;
    cudaGetSymbolAddress((void**)&hh2,  g_hh2);
    cudaGetSymbolAddress((void**)&hl2,  g_hl2);
    cudaGetSymbolAddress((void**)&wah2, g_wah2);
    cudaGetSymbolAddress((void**)&wal2, g_wal2);
    cudaGetSymbolAddress((void**)&wph2, g_wph2);
    cudaGetSymbolAddress((void**)&wpl2, g_wpl2);
    cudaGetSymbolAddress((void**)&ath2, g_ath2);
    cudaGetSymbolAddress((void**)&atl2, g_atl2);

    // 0) precompute bf16 hi/lo pair-packed operands
    prep_row<<<PAIRS_H / 256, 256>>>(hidden, hh2, hl2);
    prep_colpair<<<dim3(3 * NX / 256, NX / 2), 256>>>(w_attn, wah2, wal2, 3 * NX);
    prep_colpair<<<dim3(NX / 256, NX / 2), 256>>>(w_proj, wph2, wpl2, NX);

    // 1) QKV projection -> q (scaled) / k / v bf16 hi/lo
    gemm_mma<<<dim3(3 * NX / TN, MROWS / TM), 256, GEMM_SMEM_BYTES>>>(
        hh2, hl2, wah2, wal2, b_attn, nullptr, 3 * NX, 1);

    // 1b) V row-pair repack for pure-copy flash staging
    repack_v<<<PAIRS_H / 256, 256>>>();

    // 2) Causal flash attention (double-buffered, longest-first)
    flash_mma<<<dim3(SEQ / BQ, NH, BSZ), 256, FLASH_SMEM_BYTES>>>(amask);

    // 3) Output projection -> fp32 out
    gemm_mma<<<dim3(NX / TN, MROWS / TM), 256, GEMM_SMEM_BYTES>>>(
        ath2, atl2, wph2, wpl2, b_proj, out, NX, 2);
}